// round 15
// baseline (speedup 1.0000x reference)
#include <cuda_runtime.h>
#include <cuda_fp16.h>
#include <math.h>
#include <stdint.h>

#define BATCH 16
#define SEQ   4096
#define DIM   1280
#define TOK   77
#define CDIM  768
#define HEADS 8
#define DHEAD 160
#define EPAD  192
#define JDIM  616
#define JPAD  640
#define ROWS_KV 1232
#define ROWS_KV_PAD 1280

// ---------------------------------------------------------------------------
// Scratch (static device globals)
// ---------------------------------------------------------------------------
__device__ __align__(256) float  g_S  [(size_t)BATCH*SEQ*JPAD];
__device__ __align__(256) __half g_Xf [(size_t)BATCH*SEQ*DIM];
__device__ __align__(256) __half g_Ef [(size_t)ROWS_KV_PAD*CDIM];
__device__ __align__(256) __half g_wqT[(size_t)HEADS*DIM*EPAD];
__device__ __align__(256) __half g_wkT[(size_t)HEADS*CDIM*EPAD];
__device__ __align__(256) __half g_wvT[(size_t)HEADS*CDIM*EPAD];
__device__ __align__(256) __half g_woS[(size_t)HEADS*DIM*EPAD];
__device__ __align__(256) __half g_Mqh[(size_t)HEADS*DIM*CDIM];
__device__ __align__(256) __half g_Moh[(size_t)HEADS*DIM*CDIM];
__device__ __align__(256) __half g_A  [(size_t)BATCH*JPAD*DIM];
__device__ __align__(256) __half g_B2 [(size_t)BATCH*DIM*JPAD];
__device__ __align__(256) __half g_P  [(size_t)BATCH*SEQ*JPAD];

// ---------------------------------------------------------------------------
// helpers
// ---------------------------------------------------------------------------
__device__ __forceinline__ uint32_t smem_u32(const void* p) {
    uint32_t a;
    asm("{ .reg .u64 t; cvta.to.shared.u64 t, %1; cvt.u32.u64 %0, t; }"
        : "=r"(a) : "l"(p));
    return a;
}

#define SWZ128(o) ((o) ^ (((o) >> 3) & 0x70))

__device__ __forceinline__ void cp16(uint32_t s, const void* g) {
    asm volatile("cp.async.cg.shared.global [%0], [%1], 16;" :: "r"(s), "l"(g));
}
#define CP_COMMIT() asm volatile("cp.async.commit_group;" ::: "memory")

__device__ __forceinline__ void ldsm4(uint32_t& r0, uint32_t& r1,
                                      uint32_t& r2, uint32_t& r3, uint32_t addr) {
    asm volatile("ldmatrix.sync.aligned.m8n8.x4.shared.b16 {%0,%1,%2,%3}, [%4];"
                 : "=r"(r0), "=r"(r1), "=r"(r2), "=r"(r3) : "r"(addr));
}

__device__ __forceinline__ void mma16816(float* c, uint32_t a0, uint32_t a1,
                                         uint32_t a2, uint32_t a3,
                                         uint32_t b0, uint32_t b1) {
    asm volatile(
        "mma.sync.aligned.m16n8k16.row.col.f32.f16.f16.f32 "
        "{%0,%1,%2,%3}, {%4,%5,%6,%7}, {%8,%9}, {%0,%1,%2,%3};"
        : "+f"(c[0]), "+f"(c[1]), "+f"(c[2]), "+f"(c[3])
        : "r"(a0), "r"(a1), "r"(a2), "r"(a3), "r"(b0), "r"(b1));
}

// ---------------------------------------------------------------------------
// Common GEMM config (128x128, 2 CTAs/SM, 16 warps — proven)
// Single-sync multistage mainloop: wait -> sync -> prefetch(k+2) -> compute(k)
// ---------------------------------------------------------------------------
#define KC 64
#define TILE_B 16384
#define STAGE_B (2*TILE_B)
#define NSTAGE 3
#define MM_SMEM (NSTAGE*STAGE_B)

#define MMA_MAINLOOP(baseA_, baseB_, K_)                                        \
    uint32_t soff[4], goff[4];                                                  \
    _Pragma("unroll")                                                           \
    for (int i = 0; i < 4; ++i) {                                               \
        int idx = tid + i * 256;                                                \
        int r = (idx >> 3) & 127;                                               \
        int u = idx & 7;                                                        \
        soff[i] = SWZ128((uint32_t)(r * 128 + u * 16));                         \
        goff[i] = (uint32_t)(r * ((K_) * 2) + u * 16);                          \
    }                                                                           \
    uint32_t aRowOff[2], aXor[2];                                               \
    _Pragma("unroll")                                                           \
    for (int mi = 0; mi < 2; ++mi) {                                            \
        int r = wm * 32 + mi * 16 + (lane & 15);                                \
        aRowOff[mi] = (uint32_t)(r * 128);                                      \
        aXor[mi]    = (uint32_t)((r & 7) * 16);                                 \
    }                                                                           \
    const uint32_t aG = (uint32_t)((lane >> 4) * 16);                           \
    uint32_t bRowOff[4], bXor[4];                                               \
    _Pragma("unroll")                                                           \
    for (int q = 0; q < 4; ++q) {                                               \
        int r = wn * 64 + q * 16 + (lane & 7) + ((lane >> 4) << 3);             \
        bRowOff[q] = (uint32_t)(r * 128);                                       \
        bXor[q]    = (uint32_t)((r & 7) * 16);                                  \
    }                                                                           \
    const uint32_t bG = (uint32_t)(((lane >> 3) & 1) * 16);                     \
    float acc[2][8][4];                                                         \
    _Pragma("unroll")                                                           \
    for (int mi = 0; mi < 2; ++mi)                                              \
        _Pragma("unroll")                                                       \
        for (int ni = 0; ni < 8; ++ni)                                          \
            _Pragma("unroll")                                                   \
            for (int e = 0; e < 4; ++e) acc[mi][ni][e] = 0.f;                   \
    const int nk = (K_) / KC;                                                   \
    _Pragma("unroll")                                                           \
    for (int i = 0; i < 4; ++i) {                                               \
        cp16(sbase + soff[i],          (baseA_) + goff[i]);                     \
        cp16(sbase + TILE_B + soff[i], (baseB_) + goff[i]);                     \
    }                                                                           \
    CP_COMMIT();                                                                \
    _Pragma("unroll")                                                           \
    for (int i = 0; i < 4; ++i) {                                               \
        cp16(sbase + STAGE_B + soff[i],          (baseA_) + goff[i] + 128);     \
        cp16(sbase + STAGE_B + TILE_B + soff[i], (baseB_) + goff[i] + 128);     \
    }                                                                           \
    CP_COMMIT();                                                                \
    _Pragma("unroll")                                                           \
    for (int i = 0; i < 4; ++i) goff[i] += 256;                                 \
    for (int k = 0; k < nk; ++k) {                                              \
        if (k + 1 < nk) {                                                       \
            asm volatile("cp.async.wait_group 1;" ::: "memory");                \
        } else {                                                                \
            asm volatile("cp.async.wait_group 0;" ::: "memory");                \
        }                                                                       \
        __syncthreads();                                                        \
        if (k + 2 < nk) {                                                       \
            const uint32_t sb = sbase + ((k + 2) % NSTAGE) * STAGE_B;           \
            _Pragma("unroll")                                                   \
            for (int i = 0; i < 4; ++i) {                                       \
                cp16(sb + soff[i],          (baseA_) + goff[i]);                \
                cp16(sb + TILE_B + soff[i], (baseB_) + goff[i]);                \
            }                                                                   \
            CP_COMMIT();                                                        \
            _Pragma("unroll")                                                   \
            for (int i = 0; i < 4; ++i) goff[i] += 128;                         \
        }                                                                       \
        const uint32_t aT = sbase + (k % NSTAGE) * STAGE_B;                     \
        const uint32_t bT = aT + TILE_B;                                        \
        _Pragma("unroll")                                                       \
        for (int kk = 0; kk < 4; ++kk) {                                        \
            const uint32_t kb = (uint32_t)(kk * 32);                            \
            uint32_t a[2][4];                                                   \
            _Pragma("unroll")                                                   \
            for (int mi = 0; mi < 2; ++mi)                                      \
                ldsm4(a[mi][0], a[mi][1], a[mi][2], a[mi][3],                   \
                      aT + aRowOff[mi] + ((aG + kb) ^ aXor[mi]));               \
            uint32_t b[4][4];                                                   \
            _Pragma("unroll")                                                   \
            for (int q = 0; q < 4; ++q)                                         \
                ldsm4(b[q][0], b[q][1], b[q][2], b[q][3],                       \
                      bT + bRowOff[q] + ((bG + kb) ^ bXor[q]));                 \
            _Pragma("unroll")                                                   \
            for (int mi = 0; mi < 2; ++mi)                                      \
                _Pragma("unroll")                                               \
                for (int q = 0; q < 4; ++q) {                                   \
                    mma16816(acc[mi][q * 2 + 0],                                \
                             a[mi][0], a[mi][1], a[mi][2], a[mi][3],            \
                             b[q][0], b[q][1]);                                 \
                    mma16816(acc[mi][q * 2 + 1],                                \
                             a[mi][0], a[mi][1], a[mi][2], a[mi][3],            \
                             b[q][2], b[q][3]);                                 \
                }                                                               \
        }                                                                       \
    }

// ---------------------------------------------------------------------------
// mma_gemm (128x128): fp32 output, optional bias — the two big GEMMs
// ---------------------------------------------------------------------------
__global__ __launch_bounds__(256, 2)
void mma_gemm(const __half* __restrict__ A, const __half* __restrict__ B,
              float* __restrict__ C, const float* __restrict__ bias,
              int K, int ldc, long sA, long sB, long sC)
{
    extern __shared__ __align__(1024) char smem[];
    const uint32_t sbase = smem_u32(smem);
    const int tid  = threadIdx.x;
    const int wid  = tid >> 5;
    const int lane = tid & 31;
    const int wm   = wid & 3;
    const int wn   = wid >> 2;

    const char* baseA = (const char*)(A + (long)blockIdx.z * sA
                                        + (long)(blockIdx.y * 128) * K);
    const char* baseB = (const char*)(B + (long)blockIdx.z * sB
                                        + (long)(blockIdx.x * 128) * K);

    MMA_MAINLOOP(baseA, baseB, K)

    const int row0 = blockIdx.y * 128 + wm * 32 + (lane >> 2);
    const int col0 = blockIdx.x * 128 + wn * 64 + (lane & 3) * 2;
    float* Cb = C + (long)blockIdx.z * sC;
    #pragma unroll
    for (int mi = 0; mi < 2; ++mi) {
        #pragma unroll
        for (int ni = 0; ni < 8; ++ni) {
            const int r = row0 + mi * 16;
            const int c = col0 + ni * 8;
            float bx = 0.f, by = 0.f;
            if (bias) { bx = bias[c]; by = bias[c + 1]; }
            float2 v0 = make_float2(acc[mi][ni][0] + bx, acc[mi][ni][1] + by);
            float2 v1 = make_float2(acc[mi][ni][2] + bx, acc[mi][ni][3] + by);
            *reinterpret_cast<float2*>(Cb + (long)r * ldc + c)       = v0;
            *reinterpret_cast<float2*>(Cb + (long)(r + 8) * ldc + c) = v1;
        }
    }
}

// ---------------------------------------------------------------------------
// mma_gemm_hm: merged Mq/Mo prep. z=0..15: z<8 -> Mq head z; z>=8 -> Mo head z-8.
// ---------------------------------------------------------------------------
__global__ __launch_bounds__(256, 2)
void mma_gemm_hm(const __half* __restrict__ WqT, const __half* __restrict__ WkT,
                 const __half* __restrict__ WoS, const __half* __restrict__ WvT,
                 __half* __restrict__ Mq, __half* __restrict__ Mo, float qscale)
{
    const int K = EPAD;
    extern __shared__ __align__(1024) char smem[];
    const uint32_t sbase = smem_u32(smem);
    const int tid  = threadIdx.x;
    const int wid  = tid >> 5;
    const int lane = tid & 31;
    const int wm   = wid & 3;
    const int wn   = wid >> 2;

    const int z    = blockIdx.z;
    const bool isQ = (z < 8);
    const int h    = z & 7;
    const __half* Ah = isQ ? (WqT + (long)h * DIM * EPAD)
                           : (WoS + (long)h * DIM * EPAD);
    const __half* Bh = isQ ? (WkT + (long)h * CDIM * EPAD)
                           : (WvT + (long)h * CDIM * EPAD);
    const float scale = isQ ? qscale : 1.f;
    __half* Cdst = (isQ ? Mq : Mo) + (long)h * DIM * CDIM;

    const char* baseA = (const char*)(Ah + (long)(blockIdx.y * 128) * K);
    const char* baseB = (const char*)(Bh + (long)(blockIdx.x * 128) * K);

    MMA_MAINLOOP(baseA, baseB, K)

    const int row0 = blockIdx.y * 128 + wm * 32 + (lane >> 2);
    const int col0 = blockIdx.x * 128 + wn * 64 + (lane & 3) * 2;
    #pragma unroll
    for (int mi = 0; mi < 2; ++mi) {
        #pragma unroll
        for (int ni = 0; ni < 8; ++ni) {
            const int r = row0 + mi * 16;
            const int c = col0 + ni * 8;
            __half2 v0 = __floats2half2_rn(acc[mi][ni][0] * scale,
                                           acc[mi][ni][1] * scale);
            __half2 v1 = __floats2half2_rn(acc[mi][ni][2] * scale,
                                           acc[mi][ni][3] * scale);
            *reinterpret_cast<__half2*>(Cdst + (long)r * CDIM + c)       = v0;
            *reinterpret_cast<__half2*>(Cdst + (long)(r + 8) * CDIM + c) = v1;
        }
    }
}

// ---------------------------------------------------------------------------
// mma_gemm_fafb: merged Afold/B2 GEMM + overlapped X-cvt plane (z=0).
// ---------------------------------------------------------------------------
__global__ __launch_bounds__(256, 2)
void mma_gemm_fafb(const __half* __restrict__ Ef, const __half* __restrict__ Mq,
                   const __half* __restrict__ Mo,
                   __half* __restrict__ Adst, __half* __restrict__ B2dst,
                   const float4* __restrict__ X4, __half2* __restrict__ Xf2)
{
    const int K = CDIM;
    extern __shared__ __align__(1024) char smem[];
    const uint32_t sbase = smem_u32(smem);
    const int tid  = threadIdx.x;
    const int wid  = tid >> 5;
    const int lane = tid & 31;
    const int wm   = wid & 3;
    const int wn   = wid >> 2;

    if (blockIdx.z == 0) {
        const long cta  = blockIdx.y * gridDim.x + blockIdx.x;
        const long tg   = cta * 256 + tid;
        const long gsz  = (long)gridDim.x * gridDim.y * 256;
        const long nX   = (long)BATCH * SEQ * DIM / 4;
        for (long i0 = tg; i0 < nX; i0 += gsz * 8) {
            #pragma unroll
            for (int u = 0; u < 8; ++u) {
                const long i = i0 + (long)u * gsz;
                if (i < nX) {
                    float4 v = X4[i];
                    Xf2[2 * i]     = __floats2half2_rn(v.x, v.y);
                    Xf2[2 * i + 1] = __floats2half2_rn(v.z, v.w);
                }
            }
        }
        const int PAD = JPAD - JDIM;
        const long n1 = (long)BATCH * PAD * DIM;
        const long n2 = (long)BATCH * DIM * PAD;
        const __half z = __float2half_rn(0.f);
        for (long i = tg; i < n1 + n2; i += gsz) {
            if (i < n1) {
                int b = (int)(i / (PAD * DIM));
                int rem = (int)(i % (PAD * DIM));
                int r = rem / DIM, c = rem % DIM;
                Adst[((long)b * JPAD + JDIM + r) * DIM + c] = z;
            } else {
                long j = i - n1;
                int b = (int)(j / (DIM * PAD));
                int rem = (int)(j % (DIM * PAD));
                int e = rem / PAD, t = rem % PAD;
                B2dst[((long)b * DIM + e) * JPAD + JDIM + t] = z;
            }
        }
        return;
    }

    const int z     = blockIdx.z - 1;
    const bool isFA = (z < 8);
    const int h     = z & 7;

    const char* baseA;
    const char* baseB;
    if (isFA) {
        baseA = (const char*)(Ef + (long)(blockIdx.y * 128) * K);
        baseB = (const char*)(Mq + (long)h * DIM * CDIM
                                 + (long)(blockIdx.x * 128) * K);
    } else {
        baseA = (const char*)(Mo + (long)h * DIM * CDIM
                                 + (long)(blockIdx.y * 128) * K);
        baseB = (const char*)(Ef + (long)(blockIdx.x * 128) * K);
    }

    MMA_MAINLOOP(baseA, baseB, K)

    const int row0 = blockIdx.y * 128 + wm * 32 + (lane >> 2);
    const int col0 = blockIdx.x * 128 + wn * 64 + (lane & 3) * 2;
    if (isFA) {
        #pragma unroll
        for (int mi = 0; mi < 2; ++mi) {
            #pragma unroll
            for (int sub = 0; sub < 2; ++sub) {
                const int r = row0 + mi * 16 + sub * 8;
                if (r >= ROWS_KV) continue;
                const int b = r / TOK;
                const int t = r - b * TOK;
                __half* dst = Adst + ((long)b * JPAD + h * TOK + t) * DIM;
                #pragma unroll
                for (int ni = 0; ni < 8; ++ni) {
                    const int c = col0 + ni * 8;
                    __half2 v = __floats2half2_rn(acc[mi][ni][sub * 2 + 0],
                                                  acc[mi][ni][sub * 2 + 1]);
                    *reinterpret_cast<__half2*>(dst + c) = v;
                }
            }
        }
    } else {
        #pragma unroll
        for (int mi = 0; mi < 2; ++mi) {
            #pragma unroll
            for (int ni = 0; ni < 8; ++ni) {
                #pragma unroll
                for (int e = 0; e < 4; ++e) {
                    const int r = row0 + mi * 16 + (e >> 1) * 8;
                    const int c = col0 + ni * 8 + (e & 1);
                    if (c < ROWS_KV) {
                        const int b = c / TOK;
                        const int t = c - b * TOK;
                        B2dst[((long)b * DIM + r) * JPAD + h * TOK + t] =
                            __float2half_rn(acc[mi][ni][e]);
                    }
                }
            }
        }
    }
}

// ---------------------------------------------------------------------------
// prep_all: merged weight/activation prep in ONE launch.
// grid (40, 6, 25), block 256.
//   z in [0,8)   : wq^T head z   (RD=1280, all 40 x-tiles)
//   z in [8,16)  : wk^T head z-8 (RD=768, x-tiles 0..23, rest idle)
//   z in [16,24) : wv^T head z-16
//   z == 24      : grid-stride segment: E cvt + Ef pad zero + woslice
// ---------------------------------------------------------------------------
__global__ __launch_bounds__(256) void prep_all(
    const float* __restrict__ wq, const float* __restrict__ wk,
    const float* __restrict__ wv,
    __half* __restrict__ wqT, __half* __restrict__ wkT,
    __half* __restrict__ wvT,
    const float4* __restrict__ E, __half2* __restrict__ Ef,
    __half2* __restrict__ EfPad,
    const float* __restrict__ wo, __half* __restrict__ woS)
{
    __shared__ float tile[32][33];
    const int z = blockIdx.z;

    if (z < 24) {
        const int which = z >> 3;          // 0 wq, 1 wk, 2 wv
        const int h     = z & 7;
        const float* src = (which == 0) ? wq : (which == 1) ? wk : wv;
        __half* dst      = (which == 0) ? wqT : (which == 1) ? wkT : wvT;
        const int RD     = (which == 0) ? DIM : CDIM;

        const int r0 = blockIdx.x * 32;
        if (r0 >= RD) return;
        const int e0 = blockIdx.y * 32;
        const int tx = threadIdx.x & 31;
        const int ty = threadIdx.x >> 5;
        #pragma unroll
        for (int i = 0; i < 4; ++i) {
            const int e = e0 + ty + i * 8;
            float v = 0.f;
            if (e < DHEAD) v = src[(long)(h * DHEAD + e) * RD + r0 + tx];
            tile[ty + i * 8][tx] = v;
        }
        __syncthreads();
        #pragma unroll
        for (int i = 0; i < 4; ++i) {
            const int r = r0 + ty + i * 8;
            dst[((long)h * RD + r) * EPAD + e0 + tx] =
                __float2half_rn(tile[tx][ty + i * 8]);
        }
        return;
    }

    // z == 24: merged E cvt + Ef pad zero + woslice (240 CTAs grid-stride)
    const long tg  = ((long)blockIdx.y * gridDim.x + blockIdx.x) * 256
                   + threadIdx.x;
    const long gsz = (long)gridDim.x * gridDim.y * 256;
    const long nE = (long)ROWS_KV * CDIM / 4;
    const long nP = (long)(ROWS_KV_PAD - ROWS_KV) * CDIM / 4;
    const long nW = (long)HEADS * DIM * EPAD;
    const long total = nE + nP + nW;
    const __half2 z2 = __floats2half2_rn(0.f, 0.f);
    for (long i = tg; i < total; i += gsz) {
        if (i < nE) {
            float4 v = E[i];
            Ef[2 * i]     = __floats2half2_rn(v.x, v.y);
            Ef[2 * i + 1] = __floats2half2_rn(v.z, v.w);
        } else if (i < nE + nP) {
            long j = i - nE;
            EfPad[2 * j]     = z2;
            EfPad[2 * j + 1] = z2;
        } else {
            long j = i - nE - nP;
            int ep = (int)(j % EPAD);
            long he2 = j / EPAD;
            int e2 = (int)(he2 % DIM);
            int h  = (int)(he2 / DIM);
            float v = (ep < DHEAD) ? wo[(long)e2 * DIM + h * DHEAD + ep] : 0.f;
            woS[j] = __float2half_rn(v);
        }
    }
}

// ---------------------------------------------------------------------------
// fused softmax(77-group) -> fp16 probs; zeros prob pad cols
// ---------------------------------------------------------------------------
__global__ __launch_bounds__(256) void softmax77h(const float* __restrict__ Smat,
                                                  __half* __restrict__ P)
{
    const int gw   = blockIdx.x * 8 + (threadIdx.x >> 5);
    const int lane = threadIdx.x & 31;
    const int row  = gw >> 3;
    const int h    = gw & 7;
    const long base = (long)row * JPAD + h * TOK;

    const float NEG = -1e30f;
    float x0 = Smat[base + lane];
    float x1 = Smat[base + 32 + lane];
    float x2 = (lane < 13) ? Smat[base + 64 + lane] : NEG;

    float m = fmaxf(x0, fmaxf(x1, x2));
    #pragma unroll
    for (int o = 16; o > 0; o >>= 1)
        m = fmaxf(m, __shfl_xor_sync(0xffffffffu, m, o));

    float e0 = expf(x0 - m);
    float e1 = expf(x1 - m);
    float e2 = (lane < 13) ? expf(x2 - m) : 0.f;
    float s = e0 + e1 + e2;
    #pragma unroll
    for (int o = 16; o > 0; o >>= 1)
        s += __shfl_xor_sync(0xffffffffu, s, o);

    const float inv = 1.f / s;
    P[base + lane]      = __float2half_rn(e0 * inv);
    P[base + 32 + lane] = __float2half_rn(e1 * inv);
    if (lane < 13) P[base + 64 + lane] = __float2half_rn(e2 * inv);
    if (h == 7 && lane < JPAD - JDIM)
        P[(long)row * JPAD + JDIM + lane] = __float2half_rn(0.f);
}

// ---------------------------------------------------------------------------
extern "C" void kernel_launch(void* const* d_in, const int* in_sizes, int n_in,
                              void* d_out, int out_size)
{
    const float* X  = (const float*)d_in[0];
    const float* E  = (const float*)d_in[1];
    const float* wq = (const float*)d_in[2];
    const float* wk = (const float*)d_in[3];
    const float* wv = (const float*)d_in[4];
    const float* wo = (const float*)d_in[5];
    const float* bo = (const float*)d_in[6];
    float* out = (float*)d_out;

    float *pS;
    __half *pXf, *pEf, *pWqT, *pWkT, *pWvT, *pWoS, *pMqh, *pMoh, *pA, *pB2, *pP;
    cudaGetSymbolAddress((void**)&pS,   g_S);
    cudaGetSymbolAddress((void**)&pXf,  g_Xf);
    cudaGetSymbolAddress((void**)&pEf,  g_Ef);
    cudaGetSymbolAddress((void**)&pWqT, g_wqT);
    cudaGetSymbolAddress((void**)&pWkT, g_wkT);
    cudaGetSymbolAddress((void**)&pWvT, g_wvT);
    cudaGetSymbolAddress((void**)&pWoS, g_woS);
    cudaGetSymbolAddress((void**)&pMqh, g_Mqh);
    cudaGetSymbolAddress((void**)&pMoh, g_Moh);
    cudaGetSymbolAddress((void**)&pA,   g_A);
    cudaGetSymbolAddress((void**)&pB2,  g_B2);
    cudaGetSymbolAddress((void**)&pP,   g_P);

    cudaFuncSetAttribute(mma_gemm, cudaFuncAttributeMaxDynamicSharedMemorySize,
                         MM_SMEM);
    cudaFuncSetAttribute(mma_gemm_hm, cudaFuncAttributeMaxDynamicSharedMemorySize,
                         MM_SMEM);
    cudaFuncSetAttribute(mma_gemm_fafb,
                         cudaFuncAttributeMaxDynamicSharedMemorySize, MM_SMEM);

    const float scale = 0.07905694150420949f;   // 160^-0.5

    // ALL prep in one launch: wq/wk/wv transposes + E cvt + pad + woslice
    prep_all<<<dim3(40, 6, 25), 256>>>(wq, wk, wv, pWqT, pWkT, pWvT,
                                       (const float4*)E, (__half2*)pEf,
                                       (__half2*)(pEf + (long)ROWS_KV * CDIM),
                                       wo, pWoS);

    // merged Mq/Mo prep (fp16 out, scale fused)
    mma_gemm_hm<<<dim3(CDIM / 128, DIM / 128, 2 * HEADS), 256, MM_SMEM>>>(
        pWqT, pWkT, pWoS, pWvT, pMqh, pMoh, scale);

    // merged Afold / B2 GEMMs + overlapped X cvt + pad zero (z=0 plane)
    mma_gemm_fafb<<<dim3(DIM / 128, ROWS_KV_PAD / 128, 2 * HEADS + 1), 256,
                    MM_SMEM>>>(pEf, pMqh, pMoh, pA, pB2,
                               (const float4*)X, (__half2*)pXf);

    // scores: S[b][s][j] = sum_c X[s][c] * AfoldT[j][c]
    mma_gemm<<<dim3(JPAD / 128, SEQ / 128, BATCH), 256, MM_SMEM>>>(
        pXf, pA, pS, nullptr, DIM, JPAD,
        (long)SEQ * DIM, (long)JPAD * DIM, (long)SEQ * JPAD);

    // fused softmax -> fp16 probs
    softmax77h<<<BATCH * SEQ, 256>>>(pS, pP);

    // output: out = P x B2T + bias
    mma_gemm<<<dim3(DIM / 128, SEQ / 128, BATCH), 256, MM_SMEM>>>(
        pP, pB2, out, bo, JPAD, DIM,
        (long)SEQ * JPAD, (long)DIM * JPAD, (long)SEQ * DIM);
}

// round 16
// speedup vs baseline: 1.0062x; 1.0062x over previous
#include <cuda_runtime.h>
#include <cuda_fp16.h>
#include <math.h>
#include <stdint.h>

#define BATCH 16
#define SEQ   4096
#define DIM   1280
#define TOK   77
#define CDIM  768
#define HEADS 8
#define DHEAD 160
#define EPAD  192
#define JDIM  616
#define JPAD  640
#define ROWS_KV 1232
#define ROWS_KV_PAD 1280

// ---------------------------------------------------------------------------
// Scratch (static device globals)
// ---------------------------------------------------------------------------
__device__ __align__(256) float  g_S  [(size_t)BATCH*SEQ*JPAD];
__device__ __align__(256) __half g_Xf [(size_t)BATCH*SEQ*DIM];
__device__ __align__(256) __half g_Ef [(size_t)ROWS_KV_PAD*CDIM];
__device__ __align__(256) __half g_wqT[(size_t)HEADS*DIM*EPAD];
__device__ __align__(256) __half g_wkT[(size_t)HEADS*CDIM*EPAD];
__device__ __align__(256) __half g_wvT[(size_t)HEADS*CDIM*EPAD];
__device__ __align__(256) __half g_woS[(size_t)HEADS*DIM*EPAD];
__device__ __align__(256) __half g_Mqh[(size_t)HEADS*DIM*CDIM];
__device__ __align__(256) __half g_Moh[(size_t)HEADS*DIM*CDIM];
__device__ __align__(256) __half g_A  [(size_t)BATCH*JPAD*DIM];
__device__ __align__(256) __half g_B2 [(size_t)BATCH*DIM*JPAD];
__device__ __align__(256) __half g_P  [(size_t)BATCH*SEQ*JPAD];

// ---------------------------------------------------------------------------
// helpers
// ---------------------------------------------------------------------------
__device__ __forceinline__ uint32_t smem_u32(const void* p) {
    uint32_t a;
    asm("{ .reg .u64 t; cvta.to.shared.u64 t, %1; cvt.u32.u64 %0, t; }"
        : "=r"(a) : "l"(p));
    return a;
}

#define SWZ128(o) ((o) ^ (((o) >> 3) & 0x70))

__device__ __forceinline__ void cp16(uint32_t s, const void* g) {
    asm volatile("cp.async.cg.shared.global [%0], [%1], 16;" :: "r"(s), "l"(g));
}
#define CP_COMMIT() asm volatile("cp.async.commit_group;" ::: "memory")

__device__ __forceinline__ void ldsm4(uint32_t& r0, uint32_t& r1,
                                      uint32_t& r2, uint32_t& r3, uint32_t addr) {
    asm volatile("ldmatrix.sync.aligned.m8n8.x4.shared.b16 {%0,%1,%2,%3}, [%4];"
                 : "=r"(r0), "=r"(r1), "=r"(r2), "=r"(r3) : "r"(addr));
}

__device__ __forceinline__ void mma16816(float* c, uint32_t a0, uint32_t a1,
                                         uint32_t a2, uint32_t a3,
                                         uint32_t b0, uint32_t b1) {
    asm volatile(
        "mma.sync.aligned.m16n8k16.row.col.f32.f16.f16.f32 "
        "{%0,%1,%2,%3}, {%4,%5,%6,%7}, {%8,%9}, {%0,%1,%2,%3};"
        : "+f"(c[0]), "+f"(c[1]), "+f"(c[2]), "+f"(c[3])
        : "r"(a0), "r"(a1), "r"(a2), "r"(a3), "r"(b0), "r"(b1));
}

// ---------------------------------------------------------------------------
// Common GEMM config (128x128, 2 CTAs/SM, 16 warps — proven)
// ---------------------------------------------------------------------------
#define KC 64
#define TILE_B 16384
#define STAGE_B (2*TILE_B)
#define NSTAGE 3
#define MM_SMEM (NSTAGE*STAGE_B)

#define MMA_MAINLOOP(baseA_, baseB_, K_)                                        \
    uint32_t soff[4], goff[4];                                                  \
    _Pragma("unroll")                                                           \
    for (int i = 0; i < 4; ++i) {                                               \
        int idx = tid + i * 256;                                                \
        int r = (idx >> 3) & 127;                                               \
        int u = idx & 7;                                                        \
        soff[i] = SWZ128((uint32_t)(r * 128 + u * 16));                         \
        goff[i] = (uint32_t)(r * ((K_) * 2) + u * 16);                          \
    }                                                                           \
    uint32_t aRowOff[2], aXor[2];                                               \
    _Pragma("unroll")                                                           \
    for (int mi = 0; mi < 2; ++mi) {                                            \
        int r = wm * 32 + mi * 16 + (lane & 15);                                \
        aRowOff[mi] = (uint32_t)(r * 128);                                      \
        aXor[mi]    = (uint32_t)((r & 7) * 16);                                 \
    }                                                                           \
    const uint32_t aG = (uint32_t)((lane >> 4) * 16);                           \
    uint32_t bRowOff[4], bXor[4];                                               \
    _Pragma("unroll")                                                           \
    for (int q = 0; q < 4; ++q) {                                               \
        int r = wn * 64 + q * 16 + (lane & 7) + ((lane >> 4) << 3);             \
        bRowOff[q] = (uint32_t)(r * 128);                                       \
        bXor[q]    = (uint32_t)((r & 7) * 16);                                  \
    }                                                                           \
    const uint32_t bG = (uint32_t)(((lane >> 3) & 1) * 16);                     \
    float acc[2][8][4];                                                         \
    _Pragma("unroll")                                                           \
    for (int mi = 0; mi < 2; ++mi)                                              \
        _Pragma("unroll")                                                       \
        for (int ni = 0; ni < 8; ++ni)                                          \
            _Pragma("unroll")                                                   \
            for (int e = 0; e < 4; ++e) acc[mi][ni][e] = 0.f;                   \
    const int nk = (K_) / KC;                                                   \
    _Pragma("unroll")                                                           \
    for (int i = 0; i < 4; ++i) {                                               \
        cp16(sbase + soff[i],          (baseA_) + goff[i]);                     \
        cp16(sbase + TILE_B + soff[i], (baseB_) + goff[i]);                     \
    }                                                                           \
    CP_COMMIT();                                                                \
    _Pragma("unroll")                                                           \
    for (int i = 0; i < 4; ++i) {                                               \
        cp16(sbase + STAGE_B + soff[i],          (baseA_) + goff[i] + 128);     \
        cp16(sbase + STAGE_B + TILE_B + soff[i], (baseB_) + goff[i] + 128);     \
    }                                                                           \
    CP_COMMIT();                                                                \
    _Pragma("unroll")                                                           \
    for (int i = 0; i < 4; ++i) goff[i] += 256;                                 \
    for (int k = 0; k < nk; ++k) {                                              \
        if (k + 1 < nk) {                                                       \
            asm volatile("cp.async.wait_group 1;" ::: "memory");                \
        } else {                                                                \
            asm volatile("cp.async.wait_group 0;" ::: "memory");                \
        }                                                                       \
        __syncthreads();                                                        \
        if (k + 2 < nk) {                                                       \
            const uint32_t sb = sbase + ((k + 2) % NSTAGE) * STAGE_B;           \
            _Pragma("unroll")                                                   \
            for (int i = 0; i < 4; ++i) {                                       \
                cp16(sb + soff[i],          (baseA_) + goff[i]);                \
                cp16(sb + TILE_B + soff[i], (baseB_) + goff[i]);                \
            }                                                                   \
            CP_COMMIT();                                                        \
            _Pragma("unroll")                                                   \
            for (int i = 0; i < 4; ++i) goff[i] += 128;                         \
        }                                                                       \
        const uint32_t aT = sbase + (k % NSTAGE) * STAGE_B;                     \
        const uint32_t bT = aT + TILE_B;                                        \
        _Pragma("unroll")                                                       \
        for (int kk = 0; kk < 4; ++kk) {                                        \
            const uint32_t kb = (uint32_t)(kk * 32);                            \
            uint32_t a[2][4];                                                   \
            _Pragma("unroll")                                                   \
            for (int mi = 0; mi < 2; ++mi)                                      \
                ldsm4(a[mi][0], a[mi][1], a[mi][2], a[mi][3],                   \
                      aT + aRowOff[mi] + ((aG + kb) ^ aXor[mi]));               \
            uint32_t b[4][4];                                                   \
            _Pragma("unroll")                                                   \
            for (int q = 0; q < 4; ++q)                                         \
                ldsm4(b[q][0], b[q][1], b[q][2], b[q][3],                       \
                      bT + bRowOff[q] + ((bG + kb) ^ bXor[q]));                 \
            _Pragma("unroll")                                                   \
            for (int mi = 0; mi < 2; ++mi)                                      \
                _Pragma("unroll")                                               \
                for (int q = 0; q < 4; ++q) {                                   \
                    mma16816(acc[mi][q * 2 + 0],                                \
                             a[mi][0], a[mi][1], a[mi][2], a[mi][3],            \
                             b[q][0], b[q][1]);                                 \
                    mma16816(acc[mi][q * 2 + 1],                                \
                             a[mi][0], a[mi][1], a[mi][2], a[mi][3],            \
                             b[q][2], b[q][3]);                                 \
                }                                                               \
        }                                                                       \
    }

// ---------------------------------------------------------------------------
// mma_gemm (128x128): fp32 output — the two big GEMMs.
// Register-double-buffered fragment pipeline: ldsm(kk+1) issued before mma(kk).
// ---------------------------------------------------------------------------
__global__ __launch_bounds__(256, 2)
void mma_gemm(const __half* __restrict__ A, const __half* __restrict__ B,
              float* __restrict__ C, const float* __restrict__ bias,
              int K, int ldc, long sA, long sB, long sC)
{
    extern __shared__ __align__(1024) char smem[];
    const uint32_t sbase = smem_u32(smem);
    const int tid  = threadIdx.x;
    const int wid  = tid >> 5;
    const int lane = tid & 31;
    const int wm   = wid & 3;
    const int wn   = wid >> 2;

    const char* baseA = (const char*)(A + (long)blockIdx.z * sA
                                        + (long)(blockIdx.y * 128) * K);
    const char* baseB = (const char*)(B + (long)blockIdx.z * sB
                                        + (long)(blockIdx.x * 128) * K);

    uint32_t soff[4], goff[4];
    #pragma unroll
    for (int i = 0; i < 4; ++i) {
        int idx = tid + i * 256;
        int r = (idx >> 3) & 127;
        int u = idx & 7;
        soff[i] = SWZ128((uint32_t)(r * 128 + u * 16));
        goff[i] = (uint32_t)(r * (K * 2) + u * 16);
    }

    uint32_t aRowOff[2], aXor[2];
    #pragma unroll
    for (int mi = 0; mi < 2; ++mi) {
        int r = wm * 32 + mi * 16 + (lane & 15);
        aRowOff[mi] = (uint32_t)(r * 128);
        aXor[mi]    = (uint32_t)((r & 7) * 16);
    }
    const uint32_t aG = (uint32_t)((lane >> 4) * 16);

    uint32_t bRowOff[4], bXor[4];
    #pragma unroll
    for (int q = 0; q < 4; ++q) {
        int r = wn * 64 + q * 16 + (lane & 7) + ((lane >> 4) << 3);
        bRowOff[q] = (uint32_t)(r * 128);
        bXor[q]    = (uint32_t)((r & 7) * 16);
    }
    const uint32_t bG = (uint32_t)(((lane >> 3) & 1) * 16);

    float acc[2][8][4];
    #pragma unroll
    for (int mi = 0; mi < 2; ++mi)
        #pragma unroll
        for (int ni = 0; ni < 8; ++ni)
            #pragma unroll
            for (int e = 0; e < 4; ++e) acc[mi][ni][e] = 0.f;

    const int nk = K / KC;

    #pragma unroll
    for (int i = 0; i < 4; ++i) {
        cp16(sbase + soff[i],          baseA + goff[i]);
        cp16(sbase + TILE_B + soff[i], baseB + goff[i]);
    }
    CP_COMMIT();
    #pragma unroll
    for (int i = 0; i < 4; ++i) {
        cp16(sbase + STAGE_B + soff[i],          baseA + goff[i] + 128);
        cp16(sbase + STAGE_B + TILE_B + soff[i], baseB + goff[i] + 128);
    }
    CP_COMMIT();
    #pragma unroll
    for (int i = 0; i < 4; ++i) goff[i] += 256;

    for (int k = 0; k < nk; ++k) {
        if (k + 1 < nk) {
            asm volatile("cp.async.wait_group 1;" ::: "memory");
        } else {
            asm volatile("cp.async.wait_group 0;" ::: "memory");
        }
        __syncthreads();
        if (k + 2 < nk) {
            const uint32_t sb = sbase + ((k + 2) % NSTAGE) * STAGE_B;
            #pragma unroll
            for (int i = 0; i < 4; ++i) {
                cp16(sb + soff[i],          baseA + goff[i]);
                cp16(sb + TILE_B + soff[i], baseB + goff[i]);
            }
            CP_COMMIT();
            #pragma unroll
            for (int i = 0; i < 4; ++i) goff[i] += 128;
        }
        const uint32_t aT = sbase + (k % NSTAGE) * STAGE_B;
        const uint32_t bT = aT + TILE_B;

        // fragment double buffer
        uint32_t a[2][2][4], b[2][4][4];
        #pragma unroll
        for (int mi = 0; mi < 2; ++mi)
            ldsm4(a[0][mi][0], a[0][mi][1], a[0][mi][2], a[0][mi][3],
                  aT + aRowOff[mi] + (aG ^ aXor[mi]));
        #pragma unroll
        for (int q = 0; q < 4; ++q)
            ldsm4(b[0][q][0], b[0][q][1], b[0][q][2], b[0][q][3],
                  bT + bRowOff[q] + (bG ^ bXor[q]));

        #pragma unroll
        for (int kk = 0; kk < 4; ++kk) {
            const int cur = kk & 1;
            const int nxt = cur ^ 1;
            if (kk < 3) {
                const uint32_t kb = (uint32_t)((kk + 1) * 32);
                #pragma unroll
                for (int mi = 0; mi < 2; ++mi)
                    ldsm4(a[nxt][mi][0], a[nxt][mi][1],
                          a[nxt][mi][2], a[nxt][mi][3],
                          aT + aRowOff[mi] + ((aG + kb) ^ aXor[mi]));
                #pragma unroll
                for (int q = 0; q < 4; ++q)
                    ldsm4(b[nxt][q][0], b[nxt][q][1],
                          b[nxt][q][2], b[nxt][q][3],
                          bT + bRowOff[q] + ((bG + kb) ^ bXor[q]));
            }
            #pragma unroll
            for (int mi = 0; mi < 2; ++mi)
                #pragma unroll
                for (int q = 0; q < 4; ++q) {
                    mma16816(acc[mi][q * 2 + 0],
                             a[cur][mi][0], a[cur][mi][1],
                             a[cur][mi][2], a[cur][mi][3],
                             b[cur][q][0], b[cur][q][1]);
                    mma16816(acc[mi][q * 2 + 1],
                             a[cur][mi][0], a[cur][mi][1],
                             a[cur][mi][2], a[cur][mi][3],
                             b[cur][q][2], b[cur][q][3]);
                }
        }
    }

    const int row0 = blockIdx.y * 128 + wm * 32 + (lane >> 2);
    const int col0 = blockIdx.x * 128 + wn * 64 + (lane & 3) * 2;
    float* Cb = C + (long)blockIdx.z * sC;
    #pragma unroll
    for (int mi = 0; mi < 2; ++mi) {
        #pragma unroll
        for (int ni = 0; ni < 8; ++ni) {
            const int r = row0 + mi * 16;
            const int c = col0 + ni * 8;
            float bx = 0.f, by = 0.f;
            if (bias) { bx = bias[c]; by = bias[c + 1]; }
            float2 v0 = make_float2(acc[mi][ni][0] + bx, acc[mi][ni][1] + by);
            float2 v1 = make_float2(acc[mi][ni][2] + bx, acc[mi][ni][3] + by);
            *reinterpret_cast<float2*>(Cb + (long)r * ldc + c)       = v0;
            *reinterpret_cast<float2*>(Cb + (long)(r + 8) * ldc + c) = v1;
        }
    }
}

// ---------------------------------------------------------------------------
// mma_gemm_hm: merged Mq/Mo prep (proven macro body)
// ---------------------------------------------------------------------------
__global__ __launch_bounds__(256, 2)
void mma_gemm_hm(const __half* __restrict__ WqT, const __half* __restrict__ WkT,
                 const __half* __restrict__ WoS, const __half* __restrict__ WvT,
                 __half* __restrict__ Mq, __half* __restrict__ Mo, float qscale)
{
    const int K = EPAD;
    extern __shared__ __align__(1024) char smem[];
    const uint32_t sbase = smem_u32(smem);
    const int tid  = threadIdx.x;
    const int wid  = tid >> 5;
    const int lane = tid & 31;
    const int wm   = wid & 3;
    const int wn   = wid >> 2;

    const int z    = blockIdx.z;
    const bool isQ = (z < 8);
    const int h    = z & 7;
    const __half* Ah = isQ ? (WqT + (long)h * DIM * EPAD)
                           : (WoS + (long)h * DIM * EPAD);
    const __half* Bh = isQ ? (WkT + (long)h * CDIM * EPAD)
                           : (WvT + (long)h * CDIM * EPAD);
    const float scale = isQ ? qscale : 1.f;
    __half* Cdst = (isQ ? Mq : Mo) + (long)h * DIM * CDIM;

    const char* baseA = (const char*)(Ah + (long)(blockIdx.y * 128) * K);
    const char* baseB = (const char*)(Bh + (long)(blockIdx.x * 128) * K);

    MMA_MAINLOOP(baseA, baseB, K)

    const int row0 = blockIdx.y * 128 + wm * 32 + (lane >> 2);
    const int col0 = blockIdx.x * 128 + wn * 64 + (lane & 3) * 2;
    #pragma unroll
    for (int mi = 0; mi < 2; ++mi) {
        #pragma unroll
        for (int ni = 0; ni < 8; ++ni) {
            const int r = row0 + mi * 16;
            const int c = col0 + ni * 8;
            __half2 v0 = __floats2half2_rn(acc[mi][ni][0] * scale,
                                           acc[mi][ni][1] * scale);
            __half2 v1 = __floats2half2_rn(acc[mi][ni][2] * scale,
                                           acc[mi][ni][3] * scale);
            *reinterpret_cast<__half2*>(Cdst + (long)r * CDIM + c)       = v0;
            *reinterpret_cast<__half2*>(Cdst + (long)(r + 8) * CDIM + c) = v1;
        }
    }
}

// ---------------------------------------------------------------------------
// mma_gemm_fafb: merged Afold/B2 GEMM + overlapped X-cvt plane (z=0).
// ---------------------------------------------------------------------------
__global__ __launch_bounds__(256, 2)
void mma_gemm_fafb(const __half* __restrict__ Ef, const __half* __restrict__ Mq,
                   const __half* __restrict__ Mo,
                   __half* __restrict__ Adst, __half* __restrict__ B2dst,
                   const float4* __restrict__ X4, __half2* __restrict__ Xf2)
{
    const int K = CDIM;
    extern __shared__ __align__(1024) char smem[];
    const uint32_t sbase = smem_u32(smem);
    const int tid  = threadIdx.x;
    const int wid  = tid >> 5;
    const int lane = tid & 31;
    const int wm   = wid & 3;
    const int wn   = wid >> 2;

    if (blockIdx.z == 0) {
        const long cta  = blockIdx.y * gridDim.x + blockIdx.x;
        const long tg   = cta * 256 + tid;
        const long gsz  = (long)gridDim.x * gridDim.y * 256;
        const long nX   = (long)BATCH * SEQ * DIM / 4;
        for (long i0 = tg; i0 < nX; i0 += gsz * 8) {
            #pragma unroll
            for (int u = 0; u < 8; ++u) {
                const long i = i0 + (long)u * gsz;
                if (i < nX) {
                    float4 v = X4[i];
                    Xf2[2 * i]     = __floats2half2_rn(v.x, v.y);
                    Xf2[2 * i + 1] = __floats2half2_rn(v.z, v.w);
                }
            }
        }
        const int PAD = JPAD - JDIM;
        const long n1 = (long)BATCH * PAD * DIM;
        const long n2 = (long)BATCH * DIM * PAD;
        const __half z = __float2half_rn(0.f);
        for (long i = tg; i < n1 + n2; i += gsz) {
            if (i < n1) {
                int b = (int)(i / (PAD * DIM));
                int rem = (int)(i % (PAD * DIM));
                int r = rem / DIM, c = rem % DIM;
                Adst[((long)b * JPAD + JDIM + r) * DIM + c] = z;
            } else {
                long j = i - n1;
                int b = (int)(j / (DIM * PAD));
                int rem = (int)(j % (DIM * PAD));
                int e = rem / PAD, t = rem % PAD;
                B2dst[((long)b * DIM + e) * JPAD + JDIM + t] = z;
            }
        }
        return;
    }

    const int z     = blockIdx.z - 1;
    const bool isFA = (z < 8);
    const int h     = z & 7;

    const char* baseA;
    const char* baseB;
    if (isFA) {
        baseA = (const char*)(Ef + (long)(blockIdx.y * 128) * K);
        baseB = (const char*)(Mq + (long)h * DIM * CDIM
                                 + (long)(blockIdx.x * 128) * K);
    } else {
        baseA = (const char*)(Mo + (long)h * DIM * CDIM
                                 + (long)(blockIdx.y * 128) * K);
        baseB = (const char*)(Ef + (long)(blockIdx.x * 128) * K);
    }

    MMA_MAINLOOP(baseA, baseB, K)

    const int row0 = blockIdx.y * 128 + wm * 32 + (lane >> 2);
    const int col0 = blockIdx.x * 128 + wn * 64 + (lane & 3) * 2;
    if (isFA) {
        #pragma unroll
        for (int mi = 0; mi < 2; ++mi) {
            #pragma unroll
            for (int sub = 0; sub < 2; ++sub) {
                const int r = row0 + mi * 16 + sub * 8;
                if (r >= ROWS_KV) continue;
                const int b = r / TOK;
                const int t = r - b * TOK;
                __half* dst = Adst + ((long)b * JPAD + h * TOK + t) * DIM;
                #pragma unroll
                for (int ni = 0; ni < 8; ++ni) {
                    const int c = col0 + ni * 8;
                    __half2 v = __floats2half2_rn(acc[mi][ni][sub * 2 + 0],
                                                  acc[mi][ni][sub * 2 + 1]);
                    *reinterpret_cast<__half2*>(dst + c) = v;
                }
            }
        }
    } else {
        #pragma unroll
        for (int mi = 0; mi < 2; ++mi) {
            #pragma unroll
            for (int ni = 0; ni < 8; ++ni) {
                #pragma unroll
                for (int e = 0; e < 4; ++e) {
                    const int r = row0 + mi * 16 + (e >> 1) * 8;
                    const int c = col0 + ni * 8 + (e & 1);
                    if (c < ROWS_KV) {
                        const int b = c / TOK;
                        const int t = c - b * TOK;
                        B2dst[((long)b * DIM + r) * JPAD + h * TOK + t] =
                            __float2half_rn(acc[mi][ni][e]);
                    }
                }
            }
        }
    }
}

// ---------------------------------------------------------------------------
// transpose+pad: src[h*160+e][RD] fp32 -> dst[h][RD][EPAD] fp16
// ---------------------------------------------------------------------------
__global__ __launch_bounds__(256) void transpose_pad(
    const float* __restrict__ src, __half* __restrict__ dst, int RD)
{
    __shared__ float tile[32][33];
    const int tx = threadIdx.x & 31;
    const int ty = threadIdx.x >> 5;
    const int r0 = blockIdx.x * 32;
    const int e0 = blockIdx.y * 32;
    const int h  = blockIdx.z;
    #pragma unroll
    for (int i = 0; i < 4; ++i) {
        const int e = e0 + ty + i * 8;
        float v = 0.f;
        if (e < DHEAD) v = src[(long)(h * DHEAD + e) * RD + r0 + tx];
        tile[ty + i * 8][tx] = v;
    }
    __syncthreads();
    #pragma unroll
    for (int i = 0; i < 4; ++i) {
        const int r = r0 + ty + i * 8;
        dst[((long)h * RD + r) * EPAD + e0 + tx] =
            __float2half_rn(tile[tx][ty + i * 8]);
    }
}

// ---------------------------------------------------------------------------
// prep_small: E fp32->fp16 (+ Ef pad-row zero) + woslice, merged grid-stride.
// ---------------------------------------------------------------------------
__global__ void prep_small(const float4* __restrict__ E, __half2* __restrict__ Ef,
                           __half2* __restrict__ EfPad,
                           const float* __restrict__ wo, __half* __restrict__ woS)
{
    const long nE = (long)ROWS_KV * CDIM / 4;
    const long nP = (long)(ROWS_KV_PAD - ROWS_KV) * CDIM / 4;
    const long nW = (long)HEADS * DIM * EPAD;
    const long total = nE + nP + nW;
    const __half2 z2 = __floats2half2_rn(0.f, 0.f);
    for (long i = (long)blockIdx.x * blockDim.x + threadIdx.x; i < total;
         i += (long)gridDim.x * blockDim.x) {
        if (i < nE) {
            float4 v = E[i];
            Ef[2 * i]     = __floats2half2_rn(v.x, v.y);
            Ef[2 * i + 1] = __floats2half2_rn(v.z, v.w);
        } else if (i < nE + nP) {
            long j = i - nE;
            EfPad[2 * j]     = z2;
            EfPad[2 * j + 1] = z2;
        } else {
            long j = i - nE - nP;
            int ep = (int)(j % EPAD);
            long he2 = j / EPAD;
            int e2 = (int)(he2 % DIM);
            int h  = (int)(he2 / DIM);
            float v = (ep < DHEAD) ? wo[(long)e2 * DIM + h * DHEAD + ep] : 0.f;
            woS[j] = __float2half_rn(v);
        }
    }
}

// ---------------------------------------------------------------------------
// fused softmax(77-group) -> fp16 probs; zeros prob pad cols
// ---------------------------------------------------------------------------
__global__ __launch_bounds__(256) void softmax77h(const float* __restrict__ Smat,
                                                  __half* __restrict__ P)
{
    const int gw   = blockIdx.x * 8 + (threadIdx.x >> 5);
    const int lane = threadIdx.x & 31;
    const int row  = gw >> 3;
    const int h    = gw & 7;
    const long base = (long)row * JPAD + h * TOK;

    const float NEG = -1e30f;
    float x0 = Smat[base + lane];
    float x1 = Smat[base + 32 + lane];
    float x2 = (lane < 13) ? Smat[base + 64 + lane] : NEG;

    float m = fmaxf(x0, fmaxf(x1, x2));
    #pragma unroll
    for (int o = 16; o > 0; o >>= 1)
        m = fmaxf(m, __shfl_xor_sync(0xffffffffu, m, o));

    float e0 = expf(x0 - m);
    float e1 = expf(x1 - m);
    float e2 = (lane < 13) ? expf(x2 - m) : 0.f;
    float s = e0 + e1 + e2;
    #pragma unroll
    for (int o = 16; o > 0; o >>= 1)
        s += __shfl_xor_sync(0xffffffffu, s, o);

    const float inv = 1.f / s;
    P[base + lane]      = __float2half_rn(e0 * inv);
    P[base + 32 + lane] = __float2half_rn(e1 * inv);
    if (lane < 13) P[base + 64 + lane] = __float2half_rn(e2 * inv);
    if (h == 7 && lane < JPAD - JDIM)
        P[(long)row * JPAD + JDIM + lane] = __float2half_rn(0.f);
}

// ---------------------------------------------------------------------------
extern "C" void kernel_launch(void* const* d_in, const int* in_sizes, int n_in,
                              void* d_out, int out_size)
{
    const float* X  = (const float*)d_in[0];
    const float* E  = (const float*)d_in[1];
    const float* wq = (const float*)d_in[2];
    const float* wk = (const float*)d_in[3];
    const float* wv = (const float*)d_in[4];
    const float* wo = (const float*)d_in[5];
    const float* bo = (const float*)d_in[6];
    float* out = (float*)d_out;

    float *pS;
    __half *pXf, *pEf, *pWqT, *pWkT, *pWvT, *pWoS, *pMqh, *pMoh, *pA, *pB2, *pP;
    cudaGetSymbolAddress((void**)&pS,   g_S);
    cudaGetSymbolAddress((void**)&pXf,  g_Xf);
    cudaGetSymbolAddress((void**)&pEf,  g_Ef);
    cudaGetSymbolAddress((void**)&pWqT, g_wqT);
    cudaGetSymbolAddress((void**)&pWkT, g_wkT);
    cudaGetSymbolAddress((void**)&pWvT, g_wvT);
    cudaGetSymbolAddress((void**)&pWoS, g_woS);
    cudaGetSymbolAddress((void**)&pMqh, g_Mqh);
    cudaGetSymbolAddress((void**)&pMoh, g_Moh);
    cudaGetSymbolAddress((void**)&pA,   g_A);
    cudaGetSymbolAddress((void**)&pB2,  g_B2);
    cudaGetSymbolAddress((void**)&pP,   g_P);

    cudaFuncSetAttribute(mma_gemm, cudaFuncAttributeMaxDynamicSharedMemorySize,
                         MM_SMEM);
    cudaFuncSetAttribute(mma_gemm_hm, cudaFuncAttributeMaxDynamicSharedMemorySize,
                         MM_SMEM);
    cudaFuncSetAttribute(mma_gemm_fafb,
                         cudaFuncAttributeMaxDynamicSharedMemorySize, MM_SMEM);

    const float scale = 0.07905694150420949f;   // 160^-0.5

    // E cvt + Ef pad zero + woslice (fafb inputs)
    prep_small<<<1024, 256>>>((const float4*)E, (__half2*)pEf,
                              (__half2*)(pEf + (long)ROWS_KV * CDIM), wo, pWoS);

    // weight transposes (hm inputs)
    transpose_pad<<<dim3(DIM / 32, EPAD / 32, HEADS), 256>>>(wq, pWqT, DIM);
    transpose_pad<<<dim3(CDIM / 32, EPAD / 32, HEADS), 256>>>(wk, pWkT, CDIM);
    transpose_pad<<<dim3(CDIM / 32, EPAD / 32, HEADS), 256>>>(wv, pWvT, CDIM);

    // merged Mq/Mo prep (fp16 out, scale fused)
    mma_gemm_hm<<<dim3(CDIM / 128, DIM / 128, 2 * HEADS), 256, MM_SMEM>>>(
        pWqT, pWkT, pWoS, pWvT, pMqh, pMoh, scale);

    // merged Afold / B2 GEMMs + overlapped X cvt + pad zero (z=0 plane)
    mma_gemm_fafb<<<dim3(DIM / 128, ROWS_KV_PAD / 128, 2 * HEADS + 1), 256,
                    MM_SMEM>>>(pEf, pMqh, pMoh, pA, pB2,
                               (const float4*)X, (__half2*)pXf);

    // scores: S[b][s][j] = sum_c X[s][c] * AfoldT[j][c]  (pipelined frags)
    mma_gemm<<<dim3(JPAD / 128, SEQ / 128, BATCH), 256, MM_SMEM>>>(
        pXf, pA, pS, nullptr, DIM, JPAD,
        (long)SEQ * DIM, (long)JPAD * DIM, (long)SEQ * JPAD);

    // fused softmax -> fp16 probs
    softmax77h<<<BATCH * SEQ, 256>>>(pS, pP);

    // output: out = P x B2T + bias  (pipelined frags)
    mma_gemm<<<dim3(DIM / 128, SEQ / 128, BATCH), 256, MM_SMEM>>>(
        pP, pB2, out, bo, JPAD, DIM,
        (long)SEQ * JPAD, (long)DIM * JPAD, (long)SEQ * DIM);
}

// round 17
// speedup vs baseline: 1.0187x; 1.0124x over previous
#include <cuda_runtime.h>
#include <cuda_fp16.h>
#include <math.h>
#include <stdint.h>

#define BATCH 16
#define SEQ   4096
#define DIM   1280
#define TOK   77
#define CDIM  768
#define HEADS 8
#define DHEAD 160
#define EPAD  192
#define JDIM  616
#define JPAD  640
#define ROWS_KV 1232
#define ROWS_KV_PAD 1280

// ---------------------------------------------------------------------------
// Scratch (static device globals)
// ---------------------------------------------------------------------------
__device__ __align__(256) float  g_S  [(size_t)BATCH*SEQ*JPAD];
__device__ __align__(256) __half g_Xf [(size_t)BATCH*SEQ*DIM];
__device__ __align__(256) __half g_Ef [(size_t)ROWS_KV_PAD*CDIM];
__device__ __align__(256) __half g_wqT[(size_t)HEADS*DIM*EPAD];
__device__ __align__(256) __half g_wkT[(size_t)HEADS*CDIM*EPAD];
__device__ __align__(256) __half g_wvT[(size_t)HEADS*CDIM*EPAD];
__device__ __align__(256) __half g_woS[(size_t)HEADS*DIM*EPAD];
__device__ __align__(256) __half g_Mqh[(size_t)HEADS*DIM*CDIM];
__device__ __align__(256) __half g_Moh[(size_t)HEADS*DIM*CDIM];
__device__ __align__(256) __half g_A  [(size_t)BATCH*JPAD*DIM];
__device__ __align__(256) __half g_B2 [(size_t)BATCH*DIM*JPAD];
__device__ __align__(256) __half g_P  [(size_t)BATCH*SEQ*JPAD];

// ---------------------------------------------------------------------------
// helpers
// ---------------------------------------------------------------------------
__device__ __forceinline__ uint32_t smem_u32(const void* p) {
    uint32_t a;
    asm("{ .reg .u64 t; cvta.to.shared.u64 t, %1; cvt.u32.u64 %0, t; }"
        : "=r"(a) : "l"(p));
    return a;
}

#define SWZ128(o) ((o) ^ (((o) >> 3) & 0x70))

__device__ __forceinline__ void cp16(uint32_t s, const void* g) {
    asm volatile("cp.async.cg.shared.global [%0], [%1], 16;" :: "r"(s), "l"(g));
}
#define CP_COMMIT() asm volatile("cp.async.commit_group;" ::: "memory")

__device__ __forceinline__ void ldsm4(uint32_t& r0, uint32_t& r1,
                                      uint32_t& r2, uint32_t& r3, uint32_t addr) {
    asm volatile("ldmatrix.sync.aligned.m8n8.x4.shared.b16 {%0,%1,%2,%3}, [%4];"
                 : "=r"(r0), "=r"(r1), "=r"(r2), "=r"(r3) : "r"(addr));
}

__device__ __forceinline__ void mma16816(float* c, uint32_t a0, uint32_t a1,
                                         uint32_t a2, uint32_t a3,
                                         uint32_t b0, uint32_t b1) {
    asm volatile(
        "mma.sync.aligned.m16n8k16.row.col.f32.f16.f16.f32 "
        "{%0,%1,%2,%3}, {%4,%5,%6,%7}, {%8,%9}, {%0,%1,%2,%3};"
        : "+f"(c[0]), "+f"(c[1]), "+f"(c[2]), "+f"(c[3])
        : "r"(a0), "r"(a1), "r"(a2), "r"(a3), "r"(b0), "r"(b1));
}

// ---------------------------------------------------------------------------
// Common GEMM config (128x128, 2 CTAs/SM, 16 warps — proven)
// Single-sync multistage mainloop: wait -> sync -> prefetch(k+2) -> compute(k)
// ---------------------------------------------------------------------------
#define KC 64
#define TILE_B 16384
#define STAGE_B (2*TILE_B)
#define NSTAGE 3
#define MM_SMEM (NSTAGE*STAGE_B)

#define MMA_MAINLOOP(baseA_, baseB_, K_)                                        \
    uint32_t soff[4], goff[4];                                                  \
    _Pragma("unroll")                                                           \
    for (int i = 0; i < 4; ++i) {                                               \
        int idx = tid + i * 256;                                                \
        int r = (idx >> 3) & 127;                                               \
        int u = idx & 7;                                                        \
        soff[i] = SWZ128((uint32_t)(r * 128 + u * 16));                         \
        goff[i] = (uint32_t)(r * ((K_) * 2) + u * 16);                          \
    }                                                                           \
    uint32_t aRowOff[2], aXor[2];                                               \
    _Pragma("unroll")                                                           \
    for (int mi = 0; mi < 2; ++mi) {                                            \
        int r = wm * 32 + mi * 16 + (lane & 15);                                \
        aRowOff[mi] = (uint32_t)(r * 128);                                      \
        aXor[mi]    = (uint32_t)((r & 7) * 16);                                 \
    }                                                                           \
    const uint32_t aG = (uint32_t)((lane >> 4) * 16);                           \
    uint32_t bRowOff[4], bXor[4];                                               \
    _Pragma("unroll")                                                           \
    for (int q = 0; q < 4; ++q) {                                               \
        int r = wn * 64 + q * 16 + (lane & 7) + ((lane >> 4) << 3);             \
        bRowOff[q] = (uint32_t)(r * 128);                                       \
        bXor[q]    = (uint32_t)((r & 7) * 16);                                  \
    }                                                                           \
    const uint32_t bG = (uint32_t)(((lane >> 3) & 1) * 16);                     \
    float acc[2][8][4];                                                         \
    _Pragma("unroll")                                                           \
    for (int mi = 0; mi < 2; ++mi)                                              \
        _Pragma("unroll")                                                       \
        for (int ni = 0; ni < 8; ++ni)                                          \
            _Pragma("unroll")                                                   \
            for (int e = 0; e < 4; ++e) acc[mi][ni][e] = 0.f;                   \
    const int nk = (K_) / KC;                                                   \
    _Pragma("unroll")                                                           \
    for (int i = 0; i < 4; ++i) {                                               \
        cp16(sbase + soff[i],          (baseA_) + goff[i]);                     \
        cp16(sbase + TILE_B + soff[i], (baseB_) + goff[i]);                     \
    }                                                                           \
    CP_COMMIT();                                                                \
    _Pragma("unroll")                                                           \
    for (int i = 0; i < 4; ++i) {                                               \
        cp16(sbase + STAGE_B + soff[i],          (baseA_) + goff[i] + 128);     \
        cp16(sbase + STAGE_B + TILE_B + soff[i], (baseB_) + goff[i] + 128);     \
    }                                                                           \
    CP_COMMIT();                                                                \
    _Pragma("unroll")                                                           \
    for (int i = 0; i < 4; ++i) goff[i] += 256;                                 \
    for (int k = 0; k < nk; ++k) {                                              \
        if (k + 1 < nk) {                                                       \
            asm volatile("cp.async.wait_group 1;" ::: "memory");                \
        } else {                                                                \
            asm volatile("cp.async.wait_group 0;" ::: "memory");                \
        }                                                                       \
        __syncthreads();                                                        \
        if (k + 2 < nk) {                                                       \
            const uint32_t sb = sbase + ((k + 2) % NSTAGE) * STAGE_B;           \
            _Pragma("unroll")                                                   \
            for (int i = 0; i < 4; ++i) {                                       \
                cp16(sb + soff[i],          (baseA_) + goff[i]);                \
                cp16(sb + TILE_B + soff[i], (baseB_) + goff[i]);                \
            }                                                                   \
            CP_COMMIT();                                                        \
            _Pragma("unroll")                                                   \
            for (int i = 0; i < 4; ++i) goff[i] += 128;                         \
        }                                                                       \
        const uint32_t aT = sbase + (k % NSTAGE) * STAGE_B;                     \
        const uint32_t bT = aT + TILE_B;                                        \
        _Pragma("unroll")                                                       \
        for (int kk = 0; kk < 4; ++kk) {                                        \
            const uint32_t kb = (uint32_t)(kk * 32);                            \
            uint32_t a[2][4];                                                   \
            _Pragma("unroll")                                                   \
            for (int mi = 0; mi < 2; ++mi)                                      \
                ldsm4(a[mi][0], a[mi][1], a[mi][2], a[mi][3],                   \
                      aT + aRowOff[mi] + ((aG + kb) ^ aXor[mi]));               \
            uint32_t b[4][4];                                                   \
            _Pragma("unroll")                                                   \
            for (int q = 0; q < 4; ++q)                                         \
                ldsm4(b[q][0], b[q][1], b[q][2], b[q][3],                       \
                      bT + bRowOff[q] + ((bG + kb) ^ bXor[q]));                 \
            _Pragma("unroll")                                                   \
            for (int mi = 0; mi < 2; ++mi)                                      \
                _Pragma("unroll")                                               \
                for (int q = 0; q < 4; ++q) {                                   \
                    mma16816(acc[mi][q * 2 + 0],                                \
                             a[mi][0], a[mi][1], a[mi][2], a[mi][3],            \
                             b[q][0], b[q][1]);                                 \
                    mma16816(acc[mi][q * 2 + 1],                                \
                             a[mi][0], a[mi][1], a[mi][2], a[mi][3],            \
                             b[q][2], b[q][3]);                                 \
                }                                                               \
        }                                                                       \
    }

// ---------------------------------------------------------------------------
// mma_gemm (128x128): fp32 output, optional bias — the two big GEMMs
// ---------------------------------------------------------------------------
__global__ __launch_bounds__(256, 2)
void mma_gemm(const __half* __restrict__ A, const __half* __restrict__ B,
              float* __restrict__ C, const float* __restrict__ bias,
              int K, int ldc, long sA, long sB, long sC)
{
    extern __shared__ __align__(1024) char smem[];
    const uint32_t sbase = smem_u32(smem);
    const int tid  = threadIdx.x;
    const int wid  = tid >> 5;
    const int lane = tid & 31;
    const int wm   = wid & 3;
    const int wn   = wid >> 2;

    const char* baseA = (const char*)(A + (long)blockIdx.z * sA
                                        + (long)(blockIdx.y * 128) * K);
    const char* baseB = (const char*)(B + (long)blockIdx.z * sB
                                        + (long)(blockIdx.x * 128) * K);

    MMA_MAINLOOP(baseA, baseB, K)

    const int row0 = blockIdx.y * 128 + wm * 32 + (lane >> 2);
    const int col0 = blockIdx.x * 128 + wn * 64 + (lane & 3) * 2;
    float* Cb = C + (long)blockIdx.z * sC;
    #pragma unroll
    for (int mi = 0; mi < 2; ++mi) {
        #pragma unroll
        for (int ni = 0; ni < 8; ++ni) {
            const int r = row0 + mi * 16;
            const int c = col0 + ni * 8;
            float bx = 0.f, by = 0.f;
            if (bias) { bx = bias[c]; by = bias[c + 1]; }
            float2 v0 = make_float2(acc[mi][ni][0] + bx, acc[mi][ni][1] + by);
            float2 v1 = make_float2(acc[mi][ni][2] + bx, acc[mi][ni][3] + by);
            *reinterpret_cast<float2*>(Cb + (long)r * ldc + c)       = v0;
            *reinterpret_cast<float2*>(Cb + (long)(r + 8) * ldc + c) = v1;
        }
    }
}

// ---------------------------------------------------------------------------
// mma_gemm_hm: merged Mq/Mo prep. z=0..15: z<8 -> Mq head z; z>=8 -> Mo head z-8.
// ---------------------------------------------------------------------------
__global__ __launch_bounds__(256, 2)
void mma_gemm_hm(const __half* __restrict__ WqT, const __half* __restrict__ WkT,
                 const __half* __restrict__ WoS, const __half* __restrict__ WvT,
                 __half* __restrict__ Mq, __half* __restrict__ Mo, float qscale)
{
    const int K = EPAD;
    extern __shared__ __align__(1024) char smem[];
    const uint32_t sbase = smem_u32(smem);
    const int tid  = threadIdx.x;
    const int wid  = tid >> 5;
    const int lane = tid & 31;
    const int wm   = wid & 3;
    const int wn   = wid >> 2;

    const int z    = blockIdx.z;
    const bool isQ = (z < 8);
    const int h    = z & 7;
    const __half* Ah = isQ ? (WqT + (long)h * DIM * EPAD)
                           : (WoS + (long)h * DIM * EPAD);
    const __half* Bh = isQ ? (WkT + (long)h * CDIM * EPAD)
                           : (WvT + (long)h * CDIM * EPAD);
    const float scale = isQ ? qscale : 1.f;
    __half* Cdst = (isQ ? Mq : Mo) + (long)h * DIM * CDIM;

    const char* baseA = (const char*)(Ah + (long)(blockIdx.y * 128) * K);
    const char* baseB = (const char*)(Bh + (long)(blockIdx.x * 128) * K);

    MMA_MAINLOOP(baseA, baseB, K)

    const int row0 = blockIdx.y * 128 + wm * 32 + (lane >> 2);
    const int col0 = blockIdx.x * 128 + wn * 64 + (lane & 3) * 2;
    #pragma unroll
    for (int mi = 0; mi < 2; ++mi) {
        #pragma unroll
        for (int ni = 0; ni < 8; ++ni) {
            const int r = row0 + mi * 16;
            const int c = col0 + ni * 8;
            __half2 v0 = __floats2half2_rn(acc[mi][ni][0] * scale,
                                           acc[mi][ni][1] * scale);
            __half2 v1 = __floats2half2_rn(acc[mi][ni][2] * scale,
                                           acc[mi][ni][3] * scale);
            *reinterpret_cast<__half2*>(Cdst + (long)r * CDIM + c)       = v0;
            *reinterpret_cast<__half2*>(Cdst + (long)(r + 8) * CDIM + c) = v1;
        }
    }
}

// ---------------------------------------------------------------------------
// mma_gemm_fafb: merged Afold/B2 GEMM + overlapped X-cvt plane (z=0).
// ---------------------------------------------------------------------------
__global__ __launch_bounds__(256, 2)
void mma_gemm_fafb(const __half* __restrict__ Ef, const __half* __restrict__ Mq,
                   const __half* __restrict__ Mo,
                   __half* __restrict__ Adst, __half* __restrict__ B2dst,
                   const float4* __restrict__ X4, __half2* __restrict__ Xf2)
{
    const int K = CDIM;
    extern __shared__ __align__(1024) char smem[];
    const uint32_t sbase = smem_u32(smem);
    const int tid  = threadIdx.x;
    const int wid  = tid >> 5;
    const int lane = tid & 31;
    const int wm   = wid & 3;
    const int wn   = wid >> 2;

    if (blockIdx.z == 0) {
        const long cta  = blockIdx.y * gridDim.x + blockIdx.x;
        const long tg   = cta * 256 + tid;
        const long gsz  = (long)gridDim.x * gridDim.y * 256;
        const long nX   = (long)BATCH * SEQ * DIM / 4;
        for (long i0 = tg; i0 < nX; i0 += gsz * 8) {
            #pragma unroll
            for (int u = 0; u < 8; ++u) {
                const long i = i0 + (long)u * gsz;
                if (i < nX) {
                    float4 v = X4[i];
                    Xf2[2 * i]     = __floats2half2_rn(v.x, v.y);
                    Xf2[2 * i + 1] = __floats2half2_rn(v.z, v.w);
                }
            }
        }
        const int PAD = JPAD - JDIM;
        const long n1 = (long)BATCH * PAD * DIM;
        const long n2 = (long)BATCH * DIM * PAD;
        const __half z = __float2half_rn(0.f);
        for (long i = tg; i < n1 + n2; i += gsz) {
            if (i < n1) {
                int b = (int)(i / (PAD * DIM));
                int rem = (int)(i % (PAD * DIM));
                int r = rem / DIM, c = rem % DIM;
                Adst[((long)b * JPAD + JDIM + r) * DIM + c] = z;
            } else {
                long j = i - n1;
                int b = (int)(j / (DIM * PAD));
                int rem = (int)(j % (DIM * PAD));
                int e = rem / PAD, t = rem % PAD;
                B2dst[((long)b * DIM + e) * JPAD + JDIM + t] = z;
            }
        }
        return;
    }

    const int z     = blockIdx.z - 1;
    const bool isFA = (z < 8);
    const int h     = z & 7;

    const char* baseA;
    const char* baseB;
    if (isFA) {
        baseA = (const char*)(Ef + (long)(blockIdx.y * 128) * K);
        baseB = (const char*)(Mq + (long)h * DIM * CDIM
                                 + (long)(blockIdx.x * 128) * K);
    } else {
        baseA = (const char*)(Mo + (long)h * DIM * CDIM
                                 + (long)(blockIdx.y * 128) * K);
        baseB = (const char*)(Ef + (long)(blockIdx.x * 128) * K);
    }

    MMA_MAINLOOP(baseA, baseB, K)

    const int row0 = blockIdx.y * 128 + wm * 32 + (lane >> 2);
    const int col0 = blockIdx.x * 128 + wn * 64 + (lane & 3) * 2;
    if (isFA) {
        #pragma unroll
        for (int mi = 0; mi < 2; ++mi) {
            #pragma unroll
            for (int sub = 0; sub < 2; ++sub) {
                const int r = row0 + mi * 16 + sub * 8;
                if (r >= ROWS_KV) continue;
                const int b = r / TOK;
                const int t = r - b * TOK;
                __half* dst = Adst + ((long)b * JPAD + h * TOK + t) * DIM;
                #pragma unroll
                for (int ni = 0; ni < 8; ++ni) {
                    const int c = col0 + ni * 8;
                    __half2 v = __floats2half2_rn(acc[mi][ni][sub * 2 + 0],
                                                  acc[mi][ni][sub * 2 + 1]);
                    *reinterpret_cast<__half2*>(dst + c) = v;
                }
            }
        }
    } else {
        #pragma unroll
        for (int mi = 0; mi < 2; ++mi) {
            #pragma unroll
            for (int ni = 0; ni < 8; ++ni) {
                #pragma unroll
                for (int e = 0; e < 4; ++e) {
                    const int r = row0 + mi * 16 + (e >> 1) * 8;
                    const int c = col0 + ni * 8 + (e & 1);
                    if (c < ROWS_KV) {
                        const int b = c / TOK;
                        const int t = c - b * TOK;
                        B2dst[((long)b * DIM + r) * JPAD + h * TOK + t] =
                            __float2half_rn(acc[mi][ni][e]);
                    }
                }
            }
        }
    }
}

// ---------------------------------------------------------------------------
// transpose+pad: src[h*160+e][RD] fp32 -> dst[h][RD][EPAD] fp16
// ---------------------------------------------------------------------------
__global__ __launch_bounds__(256) void transpose_pad(
    const float* __restrict__ src, __half* __restrict__ dst, int RD)
{
    __shared__ float tile[32][33];
    const int tx = threadIdx.x & 31;
    const int ty = threadIdx.x >> 5;
    const int r0 = blockIdx.x * 32;
    const int e0 = blockIdx.y * 32;
    const int h  = blockIdx.z;
    #pragma unroll
    for (int i = 0; i < 4; ++i) {
        const int e = e0 + ty + i * 8;
        float v = 0.f;
        if (e < DHEAD) v = src[(long)(h * DHEAD + e) * RD + r0 + tx];
        tile[ty + i * 8][tx] = v;
    }
    __syncthreads();
    #pragma unroll
    for (int i = 0; i < 4; ++i) {
        const int r = r0 + ty + i * 8;
        dst[((long)h * RD + r) * EPAD + e0 + tx] =
            __float2half_rn(tile[tx][ty + i * 8]);
    }
}

// ---------------------------------------------------------------------------
// prep_small: E fp32->fp16 (+ Ef pad-row zero) + woslice, merged grid-stride.
// ---------------------------------------------------------------------------
__global__ void prep_small(const float4* __restrict__ E, __half2* __restrict__ Ef,
                           __half2* __restrict__ EfPad,
                           const float* __restrict__ wo, __half* __restrict__ woS)
{
    const long nE = (long)ROWS_KV * CDIM / 4;
    const long nP = (long)(ROWS_KV_PAD - ROWS_KV) * CDIM / 4;
    const long nW = (long)HEADS * DIM * EPAD;
    const long total = nE + nP + nW;
    const __half2 z2 = __floats2half2_rn(0.f, 0.f);
    for (long i = (long)blockIdx.x * blockDim.x + threadIdx.x; i < total;
         i += (long)gridDim.x * blockDim.x) {
        if (i < nE) {
            float4 v = E[i];
            Ef[2 * i]     = __floats2half2_rn(v.x, v.y);
            Ef[2 * i + 1] = __floats2half2_rn(v.z, v.w);
        } else if (i < nE + nP) {
            long j = i - nE;
            EfPad[2 * j]     = z2;
            EfPad[2 * j + 1] = z2;
        } else {
            long j = i - nE - nP;
            int ep = (int)(j % EPAD);
            long he2 = j / EPAD;
            int e2 = (int)(he2 % DIM);
            int h  = (int)(he2 / DIM);
            float v = (ep < DHEAD) ? wo[(long)e2 * DIM + h * DHEAD + ep] : 0.f;
            woS[j] = __float2half_rn(v);
        }
    }
}

// ---------------------------------------------------------------------------
// fused softmax(77-group) -> fp16 probs; zeros prob pad cols (fast-exp path)
// ---------------------------------------------------------------------------
__global__ __launch_bounds__(256) void softmax77h(const float* __restrict__ Smat,
                                                  __half* __restrict__ P)
{
    const int gw   = blockIdx.x * 8 + (threadIdx.x >> 5);
    const int lane = threadIdx.x & 31;
    const int row  = gw >> 3;
    const int h    = gw & 7;
    const long base = (long)row * JPAD + h * TOK;

    const float NEG = -1e30f;
    float x0 = Smat[base + lane];
    float x1 = Smat[base + 32 + lane];
    float x2 = (lane < 13) ? Smat[base + 64 + lane] : NEG;

    float m = fmaxf(x0, fmaxf(x1, x2));
    #pragma unroll
    for (int o = 16; o > 0; o >>= 1)
        m = fmaxf(m, __shfl_xor_sync(0xffffffffu, m, o));

    float e0 = __expf(x0 - m);
    float e1 = __expf(x1 - m);
    float e2 = (lane < 13) ? __expf(x2 - m) : 0.f;
    float s = e0 + e1 + e2;
    #pragma unroll
    for (int o = 16; o > 0; o >>= 1)
        s += __shfl_xor_sync(0xffffffffu, s, o);

    const float inv = 1.f / s;
    P[base + lane]      = __float2half_rn(e0 * inv);
    P[base + 32 + lane] = __float2half_rn(e1 * inv);
    if (lane < 13) P[base + 64 + lane] = __float2half_rn(e2 * inv);
    if (h == 7 && lane < JPAD - JDIM)
        P[(long)row * JPAD + JDIM + lane] = __float2half_rn(0.f);
}

// ---------------------------------------------------------------------------
extern "C" void kernel_launch(void* const* d_in, const int* in_sizes, int n_in,
                              void* d_out, int out_size)
{
    const float* X  = (const float*)d_in[0];
    const float* E  = (const float*)d_in[1];
    const float* wq = (const float*)d_in[2];
    const float* wk = (const float*)d_in[3];
    const float* wv = (const float*)d_in[4];
    const float* wo = (const float*)d_in[5];
    const float* bo = (const float*)d_in[6];
    float* out = (float*)d_out;

    float *pS;
    __half *pXf, *pEf, *pWqT, *pWkT, *pWvT, *pWoS, *pMqh, *pMoh, *pA, *pB2, *pP;
    cudaGetSymbolAddress((void**)&pS,   g_S);
    cudaGetSymbolAddress((void**)&pXf,  g_Xf);
    cudaGetSymbolAddress((void**)&pEf,  g_Ef);
    cudaGetSymbolAddress((void**)&pWqT, g_wqT);
    cudaGetSymbolAddress((void**)&pWkT, g_wkT);
    cudaGetSymbolAddress((void**)&pWvT, g_wvT);
    cudaGetSymbolAddress((void**)&pWoS, g_woS);
    cudaGetSymbolAddress((void**)&pMqh, g_Mqh);
    cudaGetSymbolAddress((void**)&pMoh, g_Moh);
    cudaGetSymbolAddress((void**)&pA,   g_A);
    cudaGetSymbolAddress((void**)&pB2,  g_B2);
    cudaGetSymbolAddress((void**)&pP,   g_P);

    cudaFuncSetAttribute(mma_gemm, cudaFuncAttributeMaxDynamicSharedMemorySize,
                         MM_SMEM);
    cudaFuncSetAttribute(mma_gemm_hm, cudaFuncAttributeMaxDynamicSharedMemorySize,
                         MM_SMEM);
    cudaFuncSetAttribute(mma_gemm_fafb,
                         cudaFuncAttributeMaxDynamicSharedMemorySize, MM_SMEM);

    const float scale = 0.07905694150420949f;   // 160^-0.5

    // E cvt + Ef pad zero + woslice (fafb inputs)
    prep_small<<<1024, 256>>>((const float4*)E, (__half2*)pEf,
                              (__half2*)(pEf + (long)ROWS_KV * CDIM), wo, pWoS);

    // weight transposes (hm inputs)
    transpose_pad<<<dim3(DIM / 32, EPAD / 32, HEADS), 256>>>(wq, pWqT, DIM);
    transpose_pad<<<dim3(CDIM / 32, EPAD / 32, HEADS), 256>>>(wk, pWkT, CDIM);
    transpose_pad<<<dim3(CDIM / 32, EPAD / 32, HEADS), 256>>>(wv, pWvT, CDIM);

    // merged Mq/Mo prep (fp16 out, scale fused)
    mma_gemm_hm<<<dim3(CDIM / 128, DIM / 128, 2 * HEADS), 256, MM_SMEM>>>(
        pWqT, pWkT, pWoS, pWvT, pMqh, pMoh, scale);

    // merged Afold / B2 GEMMs + overlapped X cvt + pad zero (z=0 plane)
    mma_gemm_fafb<<<dim3(DIM / 128, ROWS_KV_PAD / 128, 2 * HEADS + 1), 256,
                    MM_SMEM>>>(pEf, pMqh, pMoh, pA, pB2,
                               (const float4*)X, (__half2*)pXf);

    // scores: S[b][s][j] = sum_c X[s][c] * AfoldT[j][c]
    mma_gemm<<<dim3(JPAD / 128, SEQ / 128, BATCH), 256, MM_SMEM>>>(
        pXf, pA, pS, nullptr, DIM, JPAD,
        (long)SEQ * DIM, (long)JPAD * DIM, (long)SEQ * JPAD);

    // fused softmax -> fp16 probs
    softmax77h<<<BATCH * SEQ, 256>>>(pS, pP);

    // output: out = P x B2T + bias
    mma_gemm<<<dim3(DIM / 128, SEQ / 128, BATCH), 256, MM_SMEM>>>(
        pP, pB2, out, bo, JPAD, DIM,
        (long)SEQ * JPAD, (long)DIM * JPAD, (long)SEQ * DIM);
}